// round 15
// baseline (speedup 1.0000x reference)
#include <cuda_runtime.h>
#include <cuda_bf16.h>
#include <cstdint>

// ---------------------------------------------------------------------------
// Problem constants
// ---------------------------------------------------------------------------
#define BB    4
#define CINC  256
#define COUTC 256
#define CMIDC 64
#define HH    64
#define WWD   64
#define HOUT  128
#define WOUT  128
#define NPIX  16384

// ---------------------------------------------------------------------------
// Scratch (__device__ globals; no allocations allowed)
// ---------------------------------------------------------------------------
__device__ __nv_bfloat16 g_xH [NPIX * CINC];       // input hi  [pix][ci]
__device__ __nv_bfloat16 g_xL [NPIX * CINC];       // input lo
__device__ __nv_bfloat16 g_mH [NPIX * CMIDC];      // mid hi    [pix][cm]
__device__ __nv_bfloat16 g_mL [NPIX * CMIDC];      // mid lo
__device__ __nv_bfloat16 g_whH [9 * COUTC * CINC]; // [tap][co][ci]
__device__ __nv_bfloat16 g_whL [9 * COUTC * CINC];
__device__ __nv_bfloat16 g_wl2H[9 * COUTC * CMIDC];
__device__ __nv_bfloat16 g_wl2L[9 * COUTC * CMIDC];
__device__ __nv_bfloat16 g_w1H [CMIDC * CINC];     // [cm][ci] (native layout)
__device__ __nv_bfloat16 g_w1L [CMIDC * CINC];
__device__ int           g_list[8][NPIX];          // seg = branch*4 + phase
__device__ int           g_cnt[8];
__device__ int           g_work;                   // persistent work counter

// tap tables per phase (phase = py*2+px). dh/dw in {0,1}, kidx = kh*3+kw
__constant__ int c_dh[4][4] = {{0,0,0,0},{0,0,0,0},{1,0,0,0},{1,1,0,0}};
__constant__ int c_dw[4][4] = {{0,0,0,0},{1,0,0,0},{0,0,0,0},{1,0,1,0}};
__constant__ int c_kx[4][4] = {{4,0,0,0},{3,5,0,0},{1,7,0,0},{0,2,6,8}};
// heavy-first seg order (nCh = 16,8,8,4,4,2,2,1)
__constant__ int c_order[8] = {3, 1, 2, 0, 7, 5, 6, 4};

// ---------------------------------------------------------------------------
// Helpers
// ---------------------------------------------------------------------------
__device__ __forceinline__ void bsplit(float v, __nv_bfloat16 &h, __nv_bfloat16 &l) {
    h = __float2bfloat16(v);
    l = __float2bfloat16(v - __bfloat162float(h));
}
__device__ __forceinline__ uint32_t smem_u32(const void* p) {
    uint32_t a;
    asm("{ .reg .u64 t; cvta.to.shared.u64 t, %1; cvt.u32.u64 %0, t; }"
        : "=r"(a) : "l"(p));
    return a;
}
__device__ __forceinline__ void ldsm4(uint32_t &r0, uint32_t &r1,
                                      uint32_t &r2, uint32_t &r3, uint32_t a) {
    asm volatile("ldmatrix.sync.aligned.m8n8.x4.shared.b16 {%0,%1,%2,%3}, [%4];"
                 : "=r"(r0), "=r"(r1), "=r"(r2), "=r"(r3) : "r"(a));
}
__device__ __forceinline__ void mma_bf16(float* c, const uint32_t* a,
                                         const uint32_t* b) {
    asm volatile(
        "mma.sync.aligned.m16n8k16.row.col.f32.bf16.bf16.f32 "
        "{%0,%1,%2,%3}, {%4,%5,%6,%7}, {%8,%9}, {%0,%1,%2,%3};"
        : "+f"(c[0]), "+f"(c[1]), "+f"(c[2]), "+f"(c[3])
        : "r"(a[0]), "r"(a[1]), "r"(a[2]), "r"(a[3]), "r"(b[0]), "r"(b[1]));
}
__device__ __forceinline__ void cpa16(uint32_t dst, const void* src, int sz) {
    asm volatile("cp.async.cg.shared.global [%0], [%1], 16, %2;"
                 :: "r"(dst), "l"(src), "r"(sz) : "memory");
}
__device__ __forceinline__ void cpa_commit() {
    asm volatile("cp.async.commit_group;" ::: "memory");
}

// ---------------------------------------------------------------------------
// K0: zero counters
// ---------------------------------------------------------------------------
__global__ void k_zero() {
    if (threadIdx.x < 8) g_cnt[threadIdx.x] = 0;
    if (threadIdx.x == 8) g_work = 0;
}

// ---------------------------------------------------------------------------
// K1: input NCHW -> NHWC bf16 hi/lo split
// ---------------------------------------------------------------------------
__global__ void k_tin(const float* __restrict__ x) {
    __shared__ float t[32][33];
    int b  = blockIdx.z;
    int p0 = blockIdx.x * 32;
    int c0 = blockIdx.y * 32;
    int tx = threadIdx.x, ty = threadIdx.y;
#pragma unroll
    for (int r = 0; r < 4; r++) {
        int c = c0 + ty + r * 8;
        t[ty + r * 8][tx] = x[((b * CINC + c) << 12) + p0 + tx];
    }
    __syncthreads();
#pragma unroll
    for (int r = 0; r < 4; r++) {
        int p = p0 + ty + r * 8;
        float v = t[tx][ty + r * 8];
        __nv_bfloat16 h, l; bsplit(v, h, l);
        int o = ((b << 12) + p) * CINC + c0 + tx;
        g_xH[o] = h;
        g_xL[o] = l;
    }
}

// ---------------------------------------------------------------------------
// K2: weight relayout + hi/lo split
// ---------------------------------------------------------------------------
__global__ void k_tw(const float* __restrict__ wh,
                     const float* __restrict__ wl2,
                     const float* __restrict__ wl1) {
    int idx = blockIdx.x * blockDim.x + threadIdx.x;
    if (idx < 9 * CINC * COUTC) {
        int ci = idx / (COUTC * 9);
        int r  = idx % (COUTC * 9);
        int co = r / 9, t = r % 9;
        __nv_bfloat16 h, l; bsplit(wh[idx], h, l);
        int o = (t * COUTC + co) * CINC + ci;
        g_whH[o] = h; g_whL[o] = l;
    }
    if (idx < 9 * CMIDC * COUTC) {
        int cm = idx / (COUTC * 9);
        int r  = idx % (COUTC * 9);
        int co = r / 9, t = r % 9;
        __nv_bfloat16 h, l; bsplit(wl2[idx], h, l);
        int o = (t * COUTC + co) * CMIDC + cm;
        g_wl2H[o] = h; g_wl2L[o] = l;
    }
    if (idx < CMIDC * CINC) {
        __nv_bfloat16 h, l; bsplit(wl1[idx], h, l);
        g_w1H[idx] = h; g_w1L[idx] = l;   // already [cm][ci]
    }
}

// ---------------------------------------------------------------------------
// K3: bottleneck GEMM via HMMA, 3-term split.  64px x 64cm per CTA (256 blk).
//     8 warps of 16px x 32cm.
// ---------------------------------------------------------------------------
#define MD_BIAS 0
#define MD_AH   1024
#define MD_AL   (MD_AH + 2*8192)
#define MD_BH   (MD_AL + 2*8192)
#define MD_BL   (MD_BH + 2*8192)
#define MD_SMEM (MD_BL + 2*8192)      // 66560

__global__ __launch_bounds__(256, 3)
void k_mid(const float* __restrict__ b_low1) {
    extern __shared__ char sm[];
    int tid = threadIdx.x;
    int m0  = blockIdx.x * 64;
    uint32_t sb = smem_u32(sm);
    float* sbias = (float*)(sm + MD_BIAS);
    if (tid < 64) sbias[tid] = b_low1[tid];

    int wid = tid >> 5, lane = tid & 31;
    int wm = wid & 3, wn = wid >> 2;    // wm: 16px group, wn: 32cm group
    float acc[4][4];
#pragma unroll
    for (int j = 0; j < 4; j++)
#pragma unroll
        for (int k = 0; k < 4; k++) acc[j][k] = 0.f;

    int srow = tid >> 2, sj0 = (tid & 3) * 2;   // 64 rows, 2 cpa16 each

    auto stage = [&](int c, int buf) {
        int koff = c * 64;
        const char* aH = (const char*)(g_xH + (size_t)(m0 + srow) * CINC + koff);
        const char* aL = (const char*)(g_xL + (size_t)(m0 + srow) * CINC + koff);
        const char* bH = (const char*)(g_w1H + (size_t)srow * CINC + koff);
        const char* bL = (const char*)(g_w1L + (size_t)srow * CINC + koff);
        uint32_t dAH = sb + MD_AH + buf * 8192 + srow * 128;
        uint32_t dAL = sb + MD_AL + buf * 8192 + srow * 128;
        uint32_t dBH = sb + MD_BH + buf * 8192 + srow * 128;
        uint32_t dBL = sb + MD_BL + buf * 8192 + srow * 128;
#pragma unroll
        for (int i = 0; i < 2; i++) {
            int j16 = sj0 + i;
            uint32_t sw = (uint32_t)((j16 ^ (srow & 7)) * 16);
            cpa16(dAH + sw, aH + j16 * 16, 16);
            cpa16(dAL + sw, aL + j16 * 16, 16);
            cpa16(dBH + sw, bH + j16 * 16, 16);
            cpa16(dBL + sw, bL + j16 * 16, 16);
        }
        cpa_commit();
    };

    stage(0, 0);
    const int nCh = 4;
    for (int c = 0; c < nCh; c++) {
        int buf = c & 1;
        if (c + 1 < nCh) {
            stage(c + 1, buf ^ 1);
            asm volatile("cp.async.wait_group 1;" ::: "memory");
        } else {
            asm volatile("cp.async.wait_group 0;" ::: "memory");
        }
        __syncthreads();
        uint32_t aBH = sb + MD_AH + buf * 8192;
        uint32_t aBL = sb + MD_AL + buf * 8192;
        uint32_t bBH = sb + MD_BH + buf * 8192;
        uint32_t bBL = sb + MD_BL + buf * 8192;
#pragma unroll
        for (int ks = 0; ks < 4; ks++) {
            uint32_t aH[4], aL[4], btH[4][2], btL[4][2];
            {
                int row = wm * 16 + (lane & 15);
                int j16 = ks * 2 + (lane >> 4);
                uint32_t sw = row * 128 + ((j16 ^ (row & 7)) * 16);
                ldsm4(aH[0], aH[1], aH[2], aH[3], aBH + sw);
                ldsm4(aL[0], aL[1], aL[2], aL[3], aBL + sw);
            }
#pragma unroll
            for (int g = 0; g < 2; g++) {
                int row = wn * 32 + g * 16 + (lane & 15);
                int j16 = ks * 2 + (lane >> 4);
                uint32_t sw = row * 128 + ((j16 ^ (row & 7)) * 16);
                uint32_t r0, r1, r2, r3;
                ldsm4(r0, r1, r2, r3, bBH + sw);
                btH[2 * g][0] = r0;     btH[2 * g][1] = r2;
                btH[2 * g + 1][0] = r1; btH[2 * g + 1][1] = r3;
                ldsm4(r0, r1, r2, r3, bBL + sw);
                btL[2 * g][0] = r0;     btL[2 * g][1] = r2;
                btL[2 * g + 1][0] = r1; btL[2 * g + 1][1] = r3;
            }
#pragma unroll
            for (int ni = 0; ni < 4; ni++) {
                mma_bf16(acc[ni], aH, btH[ni]);
                mma_bf16(acc[ni], aH, btL[ni]);
                mma_bf16(acc[ni], aL, btH[ni]);
            }
        }
        __syncthreads();
    }

    // epilogue: + bias, split to g_mH/g_mL
#pragma unroll
    for (int hb = 0; hb < 2; hb++) {
        int rloc = wm * 16 + hb * 8 + (lane >> 2);
        int pix = m0 + rloc;
#pragma unroll
        for (int ni = 0; ni < 4; ni++) {
#pragma unroll
            for (int e = 0; e < 2; e++) {
                int cm = wn * 32 + ni * 8 + (lane & 3) * 2 + e;
                float v = acc[ni][hb * 2 + e] + sbias[cm];
                __nv_bfloat16 h, l; bsplit(v, h, l);
                g_mH[(size_t)pix * CMIDC + cm] = h;
                g_mL[(size_t)pix * CMIDC + cm] = l;
            }
        }
    }
}

// ---------------------------------------------------------------------------
// K4: per-phase mask compaction
// ---------------------------------------------------------------------------
__global__ void k_compact(const float* __restrict__ mask) {
    int phase = blockIdx.y, py = phase >> 1, px = phase & 1;
    int tid = threadIdx.x;
    int pid = blockIdx.x * 256 + tid;
    int b = pid >> 12, h = (pid >> 6) & 63, w = pid & 63;
    float mv = mask[(b * HOUT + 2 * h + py) * WOUT + 2 * w + px];
    bool hi = mv > 0.5f;

    __shared__ int cHi[8], oHi[8], oLo[8];
    __shared__ int bHi, bLo;
    int lane = tid & 31, wd = tid >> 5;
    unsigned bal = __ballot_sync(0xffffffffu, hi);
    if (lane == 0) cHi[wd] = __popc(bal);
    __syncthreads();
    if (tid == 0) {
        int sh = 0, sl = 0;
        for (int i = 0; i < 8; i++) {
            oHi[i] = sh; sh += cHi[i];
            oLo[i] = sl; sl += 32 - cHi[i];
        }
        bHi = atomicAdd(&g_cnt[phase], sh);
        bLo = atomicAdd(&g_cnt[4 + phase], sl);
    }
    __syncthreads();
    unsigned lt = (1u << lane) - 1u;
    if (hi) g_list[phase][bHi + oHi[wd] + __popc(bal & lt)] = pid;
    else    g_list[4 + phase][bLo + oLo[wd] + __popc((~bal) & lt)] = pid;
}

// ---------------------------------------------------------------------------
// K5: persistent list-gathered implicit GEMM, HMMA bf16, 3-term split.
//     Work unit = (seg, 128px tile) x full 256 co, popped heavy-first from a
//     global atomic queue. 512 threads, 16 warps of 32px x 64co.
// ---------------------------------------------------------------------------
#define KM_SID  0
#define KM_BIAS 1024
#define KM_AH   2048
#define KM_AL   (KM_AH + 2*16384)
#define KM_BH   (KM_AL + 2*16384)
#define KM_BL   (KM_BH + 2*32768)
#define KM_SMEM (KM_BL + 2*32768)     // 198656

__global__ __launch_bounds__(512, 1)
void k_main(const float* __restrict__ b_high, const float* __restrict__ b_low2,
            float* __restrict__ out) {
    extern __shared__ char sm[];
    __shared__ int s_u;
    int tid = threadIdx.x;
    uint32_t sb = smem_u32(sm);
    int* sid = (int*)(sm + KM_SID);
    float* sbias = (float*)(sm + KM_BIAS);
    int wid = tid >> 5, lane = tid & 31;
    int wm = wid & 3, wn = wid >> 2;

    // heavy-first unit table (uniform per thread)
    int off[9];
    {
        int t = 0;
#pragma unroll
        for (int i = 0; i < 8; i++) {
            off[i] = t;
            t += (g_cnt[c_order[i]] + 127) >> 7;
        }
        off[8] = t;
    }

    for (;;) {
        if (tid == 0) s_u = atomicAdd(&g_work, 1);
        __syncthreads();
        int u = s_u;
        if (u >= off[8]) break;
        int oi = 0;
#pragma unroll
        for (int j = 1; j < 8; j++) if (u >= off[j]) oi = j;
        int seg = c_order[oi];
        int m0  = (u - off[oi]) << 7;
        int count = g_cnt[seg];

        int branch = seg >> 2, phase = seg & 3;
        int py = phase >> 1, px = phase & 1;
        int Kin  = branch ? CMIDC : CINC;
        int cpt  = Kin >> 6;
        int ntap = (py + 1) * (px + 1);
        int nCh  = ntap * cpt;
        const __nv_bfloat16* AH = branch ? g_mH : g_xH;
        const __nv_bfloat16* AL = branch ? g_mL : g_xL;
        const __nv_bfloat16* WH = branch ? g_wl2H : g_whH;
        const __nv_bfloat16* WL = branch ? g_wl2L : g_whL;
        const float* bias = branch ? b_low2 : b_high;

        if (tid < 128) {
            int m = m0 + tid;
            sid[tid] = g_list[seg][m < count ? m : count - 1];
        }
        if (tid < 256) sbias[tid] = bias[tid];
        __syncthreads();

        float acc[2][8][4];
#pragma unroll
        for (int i = 0; i < 2; i++)
#pragma unroll
            for (int j = 0; j < 8; j++)
#pragma unroll
                for (int k = 0; k < 4; k++) acc[i][j][k] = 0.f;

        int arow = tid >> 2, aj0 = (tid & 3) * 2;   // 2 cpa16/A tile
        int brow = tid >> 1, bj0 = (tid & 1) * 4;   // 4 cpa16/B tile

        auto stage = [&](int c, int buf) {
            int tap  = c / cpt;
            int koff = (c - tap * cpt) << 6;
            int dh = c_dh[phase][tap], dw = c_dw[phase][tap], kx = c_kx[phase][tap];
            int id = sid[arow];
            int b = id >> 12, h = (id >> 6) & 63, w = id & 63;
            int hh = h + dh, ww = w + dw;
            bool ok = (hh < HH) && (ww < WWD);
            size_t abase = (size_t)((((b << 6) + (ok ? hh : h)) << 6) + (ok ? ww : w))
                           * Kin + koff;
            const char* aH = (const char*)(AH + abase);
            const char* aL = (const char*)(AL + abase);
            uint32_t dAH = sb + KM_AH + buf * 16384 + arow * 128;
            uint32_t dAL = sb + KM_AL + buf * 16384 + arow * 128;
            int asz = ok ? 16 : 0;
#pragma unroll
            for (int i = 0; i < 2; i++) {
                int j16 = aj0 + i;
                uint32_t sw = (uint32_t)((j16 ^ (arow & 7)) * 16);
                cpa16(dAH + sw, aH + j16 * 16, asz);
                cpa16(dAL + sw, aL + j16 * 16, asz);
            }
            size_t bbase = (size_t)(kx * COUTC + brow) * Kin + koff;
            const char* bH = (const char*)(WH + bbase);
            const char* bL = (const char*)(WL + bbase);
            uint32_t dBH = sb + KM_BH + buf * 32768 + brow * 128;
            uint32_t dBL = sb + KM_BL + buf * 32768 + brow * 128;
#pragma unroll
            for (int i = 0; i < 4; i++) {
                int j16 = bj0 + i;
                uint32_t sw = (uint32_t)((j16 ^ (brow & 7)) * 16);
                cpa16(dBH + sw, bH + j16 * 16, 16);
                cpa16(dBL + sw, bL + j16 * 16, 16);
            }
            cpa_commit();
        };

        stage(0, 0);
        for (int c = 0; c < nCh; c++) {
            int buf = c & 1;
            if (c + 1 < nCh) {
                stage(c + 1, buf ^ 1);
                asm volatile("cp.async.wait_group 1;" ::: "memory");
            } else {
                asm volatile("cp.async.wait_group 0;" ::: "memory");
            }
            __syncthreads();
            uint32_t aBH = sb + KM_AH + buf * 16384;
            uint32_t aBL = sb + KM_AL + buf * 16384;
            uint32_t bBH = sb + KM_BH + buf * 32768;
            uint32_t bBL = sb + KM_BL + buf * 32768;
#pragma unroll
            for (int ks = 0; ks < 4; ks++) {
                uint32_t aH[2][4], aL[2][4], btH[8][2], btL[8][2];
#pragma unroll
                for (int mi = 0; mi < 2; mi++) {
                    int row = wm * 32 + mi * 16 + (lane & 15);
                    int j16 = ks * 2 + (lane >> 4);
                    uint32_t sw = row * 128 + ((j16 ^ (row & 7)) * 16);
                    ldsm4(aH[mi][0], aH[mi][1], aH[mi][2], aH[mi][3], aBH + sw);
                    ldsm4(aL[mi][0], aL[mi][1], aL[mi][2], aL[mi][3], aBL + sw);
                }
#pragma unroll
                for (int g = 0; g < 4; g++) {
                    int row = wn * 64 + g * 16 + (lane & 15);
                    int j16 = ks * 2 + (lane >> 4);
                    uint32_t sw = row * 128 + ((j16 ^ (row & 7)) * 16);
                    uint32_t r0, r1, r2, r3;
                    ldsm4(r0, r1, r2, r3, bBH + sw);
                    btH[2 * g][0] = r0;     btH[2 * g][1] = r2;
                    btH[2 * g + 1][0] = r1; btH[2 * g + 1][1] = r3;
                    ldsm4(r0, r1, r2, r3, bBL + sw);
                    btL[2 * g][0] = r0;     btL[2 * g][1] = r2;
                    btL[2 * g + 1][0] = r1; btL[2 * g + 1][1] = r3;
                }
#pragma unroll
                for (int mi = 0; mi < 2; mi++)
#pragma unroll
                    for (int ni = 0; ni < 8; ni++) {
                        mma_bf16(acc[mi][ni], aH[mi], btH[ni]);
                        mma_bf16(acc[mi][ni], aH[mi], btL[ni]);
                        mma_bf16(acc[mi][ni], aL[mi], btH[ni]);
                    }
            }
            __syncthreads();
        }

        // epilogue: + bias, scatter to NCHW
#pragma unroll
        for (int mi = 0; mi < 2; mi++)
#pragma unroll
            for (int hb = 0; hb < 2; hb++) {
                int rloc = wm * 32 + mi * 16 + hb * 8 + (lane >> 2);
                if (m0 + rloc >= count) continue;
                int id = sid[rloc];
                int b = id >> 12, h = (id >> 6) & 63, w = id & 63;
                int ho = 2 * h + py, wo = 2 * w + px;
                float* op = out + (((size_t)b * COUTC) * HOUT + ho) * WOUT + wo;
#pragma unroll
                for (int ni = 0; ni < 8; ni++) {
                    int n0 = wn * 64 + ni * 8 + (lane & 3) * 2;
                    op[(size_t)n0 * (HOUT * WOUT)] =
                        acc[mi][ni][hb * 2 + 0] + sbias[n0];
                    op[(size_t)(n0 + 1) * (HOUT * WOUT)] =
                        acc[mi][ni][hb * 2 + 1] + sbias[n0 + 1];
                }
            }
        __syncthreads();   // protect sid/bias before next unit overwrites
    }
}

// ---------------------------------------------------------------------------
// launch
// Inputs (metadata order): inx, mask, inv_mask, w_high, b_high,
//                          w_low1, b_low1, w_low2, b_low2
// ---------------------------------------------------------------------------
extern "C" void kernel_launch(void* const* d_in, const int* in_sizes, int n_in,
                              void* d_out, int out_size) {
    const float* inx    = (const float*)d_in[0];
    const float* mask   = (const float*)d_in[1];
    const float* w_high = (const float*)d_in[3];
    const float* b_high = (const float*)d_in[4];
    const float* w_low1 = (const float*)d_in[5];
    const float* b_low1 = (const float*)d_in[6];
    const float* w_low2 = (const float*)d_in[7];
    const float* b_low2 = (const float*)d_in[8];
    float* out = (float*)d_out;

    cudaFuncSetAttribute(k_mid,  cudaFuncAttributeMaxDynamicSharedMemorySize,
                         MD_SMEM);
    cudaFuncSetAttribute(k_main, cudaFuncAttributeMaxDynamicSharedMemorySize,
                         KM_SMEM);

    int dev = 0, nsm = 148;
    cudaGetDevice(&dev);
    cudaDeviceGetAttribute(&nsm, cudaDevAttrMultiProcessorCount, dev);

    k_zero<<<1, 32>>>();
    k_tin<<<dim3(128, 8, BB), dim3(32, 8)>>>(inx);
    k_tw<<<(9 * CINC * COUTC + 255) / 256, 256>>>(w_high, w_low2, w_low1);
    k_mid<<<NPIX / 64, 256, MD_SMEM>>>(b_low1);
    k_compact<<<dim3(NPIX / 256, 4), 256>>>(mask);
    k_main<<<nsm, 512, KM_SMEM>>>(b_high, b_low2, out);
}

// round 16
// speedup vs baseline: 1.0977x; 1.0977x over previous
#include <cuda_runtime.h>
#include <cstdint>

// ---------------------------------------------------------------------------
// Problem constants
// ---------------------------------------------------------------------------
#define BB    4
#define CINC  256
#define COUTC 256
#define CMIDC 64
#define HH    64
#define WWD   64
#define HOUT  128
#define WOUT  128
#define NPIX  16384

// ---------------------------------------------------------------------------
// Scratch (__device__ globals; no allocations allowed). All values stored
// tf32-rounded (RNA) so the hot loops do zero conversions.
// ---------------------------------------------------------------------------
__device__ float g_xT [NPIX * CINC];        // input NHWC  [pix][ci]
__device__ float g_mid[NPIX * CMIDC];       // bottleneck  [pix][cm]
__device__ float g_wh [9 * COUTC * CINC];   // [tap][co][ci]
__device__ float g_wl2[9 * COUTC * CMIDC];  // [tap][co][cm]
__device__ float g_w1 [CMIDC * CINC];       // [cm][ci] (native layout)
__device__ int   g_list[8][NPIX];           // seg = branch*4 + phase
__device__ int   g_cnt[8];

// tap tables per phase (phase = py*2+px). dh/dw in {0,1}, kidx = kh*3+kw
__constant__ int c_dh[4][4] = {{0,0,0,0},{0,0,0,0},{1,0,0,0},{1,1,0,0}};
__constant__ int c_dw[4][4] = {{0,0,0,0},{1,0,0,0},{0,0,0,0},{1,0,1,0}};
__constant__ int c_kx[4][4] = {{4,0,0,0},{3,5,0,0},{1,7,0,0},{0,2,6,8}};

// ---------------------------------------------------------------------------
// Helpers
// ---------------------------------------------------------------------------
__device__ __forceinline__ float tf32r(float x) {
    uint32_t u;
    asm("cvt.rna.tf32.f32 %0, %1;" : "=r"(u) : "f"(x));
    return __uint_as_float(u);
}
__device__ __forceinline__ uint32_t smem_u32(const void* p) {
    uint32_t a;
    asm("{ .reg .u64 t; cvta.to.shared.u64 t, %1; cvt.u32.u64 %0, t; }"
        : "=r"(a) : "l"(p));
    return a;
}
__device__ __forceinline__ void ldsm4(uint32_t &r0, uint32_t &r1,
                                      uint32_t &r2, uint32_t &r3, uint32_t a) {
    asm volatile("ldmatrix.sync.aligned.m8n8.x4.shared.b16 {%0,%1,%2,%3}, [%4];"
                 : "=r"(r0), "=r"(r1), "=r"(r2), "=r"(r3) : "r"(a));
}
// m16n8k8 tf32: A 4 regs, B 2 regs, C 4 regs (fp32)
__device__ __forceinline__ void mma_tf32(float* c, const uint32_t* a,
                                         const uint32_t* b) {
    asm volatile(
        "mma.sync.aligned.m16n8k8.row.col.f32.tf32.tf32.f32 "
        "{%0,%1,%2,%3}, {%4,%5,%6,%7}, {%8,%9}, {%0,%1,%2,%3};"
        : "+f"(c[0]), "+f"(c[1]), "+f"(c[2]), "+f"(c[3])
        : "r"(a[0]), "r"(a[1]), "r"(a[2]), "r"(a[3]), "r"(b[0]), "r"(b[1]));
}
__device__ __forceinline__ void cpa16(uint32_t dst, const void* src, int sz) {
    asm volatile("cp.async.cg.shared.global [%0], [%1], 16, %2;"
                 :: "r"(dst), "l"(src), "r"(sz) : "memory");
}
__device__ __forceinline__ void cpa_commit() {
    asm volatile("cp.async.commit_group;" ::: "memory");
}

// rows are 256B (64 tf32); 16 slots of 16B; XOR-swizzle for conflict-free ldsm
__device__ __forceinline__ uint32_t swz(int row, int j16) {
    return (uint32_t)(row * 256 + ((j16 ^ (row & 7)) * 16));
}

// ---------------------------------------------------------------------------
// K0: zero segment counters
// ---------------------------------------------------------------------------
__global__ void k_zero() {
    if (threadIdx.x < 8) g_cnt[threadIdx.x] = 0;
}

// ---------------------------------------------------------------------------
// K1: input NCHW -> NHWC, tf32-rounded
// ---------------------------------------------------------------------------
__global__ void k_tin(const float* __restrict__ x) {
    __shared__ float t[32][33];
    int b  = blockIdx.z;
    int p0 = blockIdx.x * 32;
    int c0 = blockIdx.y * 32;
    int tx = threadIdx.x, ty = threadIdx.y;
#pragma unroll
    for (int r = 0; r < 4; r++) {
        int c = c0 + ty + r * 8;
        t[ty + r * 8][tx] = x[((b * CINC + c) << 12) + p0 + tx];
    }
    __syncthreads();
#pragma unroll
    for (int r = 0; r < 4; r++) {
        int p = p0 + ty + r * 8;
        g_xT[((b << 12) + p) * CINC + c0 + tx] = tf32r(t[tx][ty + r * 8]);
    }
}

// ---------------------------------------------------------------------------
// K2: weight relayout, tf32-rounded
// ---------------------------------------------------------------------------
__global__ void k_tw(const float* __restrict__ wh,
                     const float* __restrict__ wl2,
                     const float* __restrict__ wl1) {
    int idx = blockIdx.x * blockDim.x + threadIdx.x;
    if (idx < 9 * CINC * COUTC) {
        int ci = idx / (COUTC * 9);
        int r  = idx % (COUTC * 9);
        int co = r / 9, t = r % 9;
        g_wh[(t * COUTC + co) * CINC + ci] = tf32r(wh[idx]);
    }
    if (idx < 9 * CMIDC * COUTC) {
        int cm = idx / (COUTC * 9);
        int r  = idx % (COUTC * 9);
        int co = r / 9, t = r % 9;
        g_wl2[(t * COUTC + co) * CMIDC + cm] = tf32r(wl2[idx]);
    }
    if (idx < CMIDC * CINC) {
        g_w1[idx] = tf32r(wl1[idx]);      // already [cm][ci]
    }
}

// ---------------------------------------------------------------------------
// K3: bottleneck GEMM via tf32 HMMA.  mid = x @ w1^T + b_low1.
//     M=16384(128/CTA), N=64, K=256 (4 chunks of 64). 8 warps of 32px x 32cm.
// ---------------------------------------------------------------------------
#define MD_BIAS 0
#define MD_A    1024
#define MD_B    (MD_A + 2*32768)
#define MD_SMEM (MD_B + 2*16384)      // 99328

__global__ __launch_bounds__(256, 2)
void k_mid(const float* __restrict__ b_low1) {
    extern __shared__ char sm[];
    int tid = threadIdx.x;
    int m0  = blockIdx.x * 128;
    uint32_t sb = smem_u32(sm);
    float* sbias = (float*)(sm + MD_BIAS);
    if (tid < 64) sbias[tid] = b_low1[tid];

    int wid = tid >> 5, lane = tid & 31;
    int wm = wid & 3, wn = wid >> 2;    // 4 x 32px, 2 x 32cm
    int lg = lane >> 3, lr = lane & 7;  // ldmatrix group / row-in-group
    float acc[2][4][4];
#pragma unroll
    for (int i = 0; i < 2; i++)
#pragma unroll
        for (int j = 0; j < 4; j++)
#pragma unroll
            for (int k = 0; k < 4; k++) acc[i][j][k] = 0.f;

    int arow = tid >> 1, aj0 = (tid & 1) * 8;   // 8 cpa16 per thread
    int brow = tid >> 2, bj0 = (tid & 3) * 4;   // 4 cpa16 per thread

    auto stage = [&](int c, int buf) {
        int koff = c * 64;
        const char* as = (const char*)(g_xT + (size_t)(m0 + arow) * CINC + koff);
        const char* bs = (const char*)(g_w1 + (size_t)brow * CINC + koff);
        uint32_t dA = sb + MD_A + buf * 32768;
        uint32_t dB = sb + MD_B + buf * 16384;
#pragma unroll
        for (int i = 0; i < 8; i++)
            cpa16(dA + swz(arow, aj0 + i), as + (aj0 + i) * 16, 16);
#pragma unroll
        for (int i = 0; i < 4; i++)
            cpa16(dB + swz(brow, bj0 + i), bs + (bj0 + i) * 16, 16);
        cpa_commit();
    };

    stage(0, 0);
    const int nCh = 4;
    for (int c = 0; c < nCh; c++) {
        int buf = c & 1;
        if (c + 1 < nCh) {
            stage(c + 1, buf ^ 1);
            asm volatile("cp.async.wait_group 1;" ::: "memory");
        } else {
            asm volatile("cp.async.wait_group 0;" ::: "memory");
        }
        __syncthreads();
        uint32_t aB = sb + MD_A + buf * 32768;
        uint32_t bB = sb + MD_B + buf * 16384;
#pragma unroll
        for (int ks = 0; ks < 8; ks++) {
            int j16 = ks * 2 + (lg >> 1);
            uint32_t a[2][4], bt[4][2];
#pragma unroll
            for (int mi = 0; mi < 2; mi++) {
                int row = wm * 32 + mi * 16 + (lg & 1) * 8 + lr;
                ldsm4(a[mi][0], a[mi][1], a[mi][2], a[mi][3], aB + swz(row, j16));
            }
#pragma unroll
            for (int gp = 0; gp < 2; gp++) {
                int row = wn * 32 + gp * 16 + (lg & 1) * 8 + lr;
                uint32_t r0, r1, r2, r3;
                ldsm4(r0, r1, r2, r3, bB + swz(row, j16));
                bt[2 * gp][0] = r0;     bt[2 * gp][1] = r2;
                bt[2 * gp + 1][0] = r1; bt[2 * gp + 1][1] = r3;
            }
#pragma unroll
            for (int mi = 0; mi < 2; mi++)
#pragma unroll
                for (int ni = 0; ni < 4; ni++)
                    mma_tf32(acc[mi][ni], a[mi], bt[ni]);
        }
        __syncthreads();
    }

    // epilogue: + bias, tf32-round, store
#pragma unroll
    for (int mi = 0; mi < 2; mi++)
#pragma unroll
        for (int hb = 0; hb < 2; hb++) {
            int rloc = wm * 32 + mi * 16 + hb * 8 + (lane >> 2);
            int pix = m0 + rloc;
#pragma unroll
            for (int ni = 0; ni < 4; ni++)
#pragma unroll
                for (int e = 0; e < 2; e++) {
                    int cm = wn * 32 + ni * 8 + (lane & 3) * 2 + e;
                    g_mid[(size_t)pix * CMIDC + cm] =
                        tf32r(acc[mi][ni][hb * 2 + e] + sbias[cm]);
                }
        }
}

// ---------------------------------------------------------------------------
// K4: per-phase mask compaction
// ---------------------------------------------------------------------------
__global__ void k_compact(const float* __restrict__ mask) {
    int phase = blockIdx.y, py = phase >> 1, px = phase & 1;
    int tid = threadIdx.x;
    int pid = blockIdx.x * 256 + tid;
    int b = pid >> 12, h = (pid >> 6) & 63, w = pid & 63;
    float mv = mask[(b * HOUT + 2 * h + py) * WOUT + 2 * w + px];
    bool hi = mv > 0.5f;

    __shared__ int cHi[8], oHi[8], oLo[8];
    __shared__ int bHi, bLo;
    int lane = tid & 31, wd = tid >> 5;
    unsigned bal = __ballot_sync(0xffffffffu, hi);
    if (lane == 0) cHi[wd] = __popc(bal);
    __syncthreads();
    if (tid == 0) {
        int sh = 0, sl = 0;
        for (int i = 0; i < 8; i++) {
            oHi[i] = sh; sh += cHi[i];
            oLo[i] = sl; sl += 32 - cHi[i];
        }
        bHi = atomicAdd(&g_cnt[phase], sh);
        bLo = atomicAdd(&g_cnt[4 + phase], sl);
    }
    __syncthreads();
    unsigned lt = (1u << lane) - 1u;
    if (hi) g_list[phase][bHi + oHi[wd] + __popc(bal & lt)] = pid;
    else    g_list[4 + phase][bLo + oLo[wd] + __popc((~bal) & lt)] = pid;
}

// ---------------------------------------------------------------------------
// K5: main list-gathered implicit GEMM via tf32 HMMA.
//     CTA = 128 px x 256 co, 512 threads, 16 warps of 32px x 64co.
//     K chunks of 64, cp.async double buffered.
// ---------------------------------------------------------------------------
#define KM_SID  0
#define KM_BIAS 512
#define KM_A    2048
#define KM_B    (KM_A + 2*32768)
#define KM_SMEM (KM_B + 2*65536)      // 198656

__global__ __launch_bounds__(512, 1)
void k_main(const float* __restrict__ b_high, const float* __restrict__ b_low2,
            float* __restrict__ out) {
    extern __shared__ char sm[];
    int seg   = blockIdx.y;
    int count = g_cnt[seg];
    int m0    = blockIdx.x * 128;
    if (m0 >= count) return;

    int branch = seg >> 2, phase = seg & 3;
    int py = phase >> 1, px = phase & 1;
    int Kin  = branch ? CMIDC : CINC;
    int cpt  = Kin >> 6;            // chunks per tap: 4 high / 1 low
    int ntap = (py + 1) * (px + 1);
    int nCh  = ntap * cpt;
    const float* Ab = branch ? g_mid : g_xT;
    const float* Wb = branch ? g_wl2 : g_wh;
    const float* bias = branch ? b_low2 : b_high;

    int* sid = (int*)(sm + KM_SID);
    float* sbias = (float*)(sm + KM_BIAS);
    int tid = threadIdx.x;
    if (tid < 128) {
        int m = m0 + tid;
        sid[tid] = g_list[seg][m < count ? m : count - 1];
    }
    if (tid < 256) sbias[tid] = bias[tid];
    __syncthreads();
    uint32_t sb = smem_u32(sm);

    int wid = tid >> 5, lane = tid & 31;
    int wm = wid & 3, wn = wid >> 2;    // 4 x 32px, 4 x 64co
    int lg = lane >> 3, lr = lane & 7;
    float acc[2][8][4];
#pragma unroll
    for (int i = 0; i < 2; i++)
#pragma unroll
        for (int j = 0; j < 8; j++)
#pragma unroll
            for (int k = 0; k < 4; k++) acc[i][j][k] = 0.f;

    int arow = tid >> 2, aj0 = (tid & 3) * 4;   // 4 cpa16 per thread
    int brow = tid >> 1, bj0 = (tid & 1) * 8;   // 8 cpa16 per thread

    auto stage = [&](int c, int buf) {
        int tap  = c / cpt;
        int koff = (c - tap * cpt) << 6;
        int dh = c_dh[phase][tap], dw = c_dw[phase][tap], kx = c_kx[phase][tap];
        int id = sid[arow];
        int b = id >> 12, h = (id >> 6) & 63, w = id & 63;
        int hh = h + dh, ww = w + dw;
        bool ok = (hh < HH) && (ww < WWD);
        const char* as = (const char*)(Ab +
            (size_t)((((b << 6) + (ok ? hh : h)) << 6) + (ok ? ww : w)) * Kin + koff);
        const char* bs = (const char*)(Wb +
            (size_t)(kx * COUTC + brow) * Kin + koff);
        uint32_t dA = sb + KM_A + buf * 32768;
        uint32_t dB = sb + KM_B + buf * 65536;
        int asz = ok ? 16 : 0;
#pragma unroll
        for (int i = 0; i < 4; i++)
            cpa16(dA + swz(arow, aj0 + i), as + (aj0 + i) * 16, asz);
#pragma unroll
        for (int i = 0; i < 8; i++)
            cpa16(dB + swz(brow, bj0 + i), bs + (bj0 + i) * 16, 16);
        cpa_commit();
    };

    stage(0, 0);
    for (int c = 0; c < nCh; c++) {
        int buf = c & 1;
        if (c + 1 < nCh) {
            stage(c + 1, buf ^ 1);
            asm volatile("cp.async.wait_group 1;" ::: "memory");
        } else {
            asm volatile("cp.async.wait_group 0;" ::: "memory");
        }
        __syncthreads();
        uint32_t aB = sb + KM_A + buf * 32768;
        uint32_t bB = sb + KM_B + buf * 65536;
#pragma unroll
        for (int ks = 0; ks < 8; ks++) {
            int j16 = ks * 2 + (lg >> 1);
            uint32_t a[2][4], bt[8][2];
#pragma unroll
            for (int mi = 0; mi < 2; mi++) {
                int row = wm * 32 + mi * 16 + (lg & 1) * 8 + lr;
                ldsm4(a[mi][0], a[mi][1], a[mi][2], a[mi][3], aB + swz(row, j16));
            }
#pragma unroll
            for (int gp = 0; gp < 4; gp++) {
                int row = wn * 64 + gp * 16 + (lg & 1) * 8 + lr;
                uint32_t r0, r1, r2, r3;
                ldsm4(r0, r1, r2, r3, bB + swz(row, j16));
                bt[2 * gp][0] = r0;     bt[2 * gp][1] = r2;
                bt[2 * gp + 1][0] = r1; bt[2 * gp + 1][1] = r3;
            }
#pragma unroll
            for (int mi = 0; mi < 2; mi++)
#pragma unroll
                for (int ni = 0; ni < 8; ni++)
                    mma_tf32(acc[mi][ni], a[mi], bt[ni]);
        }
        __syncthreads();
    }

    // epilogue: + bias, scatter to NCHW
#pragma unroll
    for (int mi = 0; mi < 2; mi++)
#pragma unroll
        for (int hb = 0; hb < 2; hb++) {
            int rloc = wm * 32 + mi * 16 + hb * 8 + (lane >> 2);
            if (m0 + rloc >= count) continue;
            int id = sid[rloc];
            int b = id >> 12, h = (id >> 6) & 63, w = id & 63;
            int ho = 2 * h + py, wo = 2 * w + px;
            float* op = out + (((size_t)b * COUTC) * HOUT + ho) * WOUT + wo;
#pragma unroll
            for (int ni = 0; ni < 8; ni++) {
                int n0 = wn * 64 + ni * 8 + (lane & 3) * 2;
                op[(size_t)n0 * (HOUT * WOUT)] =
                    acc[mi][ni][hb * 2 + 0] + sbias[n0];
                op[(size_t)(n0 + 1) * (HOUT * WOUT)] =
                    acc[mi][ni][hb * 2 + 1] + sbias[n0 + 1];
            }
        }
}

// ---------------------------------------------------------------------------
// launch
// Inputs (metadata order): inx, mask, inv_mask, w_high, b_high,
//                          w_low1, b_low1, w_low2, b_low2
// ---------------------------------------------------------------------------
extern "C" void kernel_launch(void* const* d_in, const int* in_sizes, int n_in,
                              void* d_out, int out_size) {
    const float* inx    = (const float*)d_in[0];
    const float* mask   = (const float*)d_in[1];
    const float* w_high = (const float*)d_in[3];
    const float* b_high = (const float*)d_in[4];
    const float* w_low1 = (const float*)d_in[5];
    const float* b_low1 = (const float*)d_in[6];
    const float* w_low2 = (const float*)d_in[7];
    const float* b_low2 = (const float*)d_in[8];
    float* out = (float*)d_out;

    cudaFuncSetAttribute(k_mid,  cudaFuncAttributeMaxDynamicSharedMemorySize,
                         MD_SMEM);
    cudaFuncSetAttribute(k_main, cudaFuncAttributeMaxDynamicSharedMemorySize,
                         KM_SMEM);

    k_zero<<<1, 32>>>();
    k_tin<<<dim3(128, 8, BB), dim3(32, 8)>>>(inx);
    k_tw<<<(9 * CINC * COUTC + 255) / 256, 256>>>(w_high, w_low2, w_low1);
    k_mid<<<NPIX / 128, 256, MD_SMEM>>>(b_low1);
    k_compact<<<dim3(NPIX / 256, 4), 256>>>(mask);
    k_main<<<dim3(NPIX / 128, 8), 512, KM_SMEM>>>(b_high, b_low2, out);
}

// round 17
// speedup vs baseline: 1.2396x; 1.1293x over previous
#include <cuda_runtime.h>
#include <cstdint>

// ---------------------------------------------------------------------------
// Problem constants
// ---------------------------------------------------------------------------
#define BB    4
#define CINC  256
#define COUTC 256
#define CMIDC 64
#define HH    64
#define WWD   64
#define HOUT  128
#define WOUT  128
#define NPIX  16384

// ---------------------------------------------------------------------------
// Scratch (__device__ globals; no allocations allowed). All values stored
// tf32-rounded (RNA) so the hot loops do zero conversions.
// ---------------------------------------------------------------------------
__device__ float g_xT [NPIX * CINC];        // input NHWC  [pix][ci]
__device__ float g_mid[NPIX * CMIDC];       // bottleneck  [pix][cm]
__device__ float g_wh [9 * COUTC * CINC];   // [tap][co][ci]
__device__ float g_wl2[9 * COUTC * CMIDC];  // [tap][co][cm]
__device__ float g_w1 [CMIDC * CINC];       // [cm][ci] (native layout)
__device__ int   g_list[8][NPIX];           // seg = branch*4 + phase
__device__ int   g_cnt[8];

// tap tables per phase (phase = py*2+px). dh/dw in {0,1}, kidx = kh*3+kw
__constant__ int c_dh[4][4] = {{0,0,0,0},{0,0,0,0},{1,0,0,0},{1,1,0,0}};
__constant__ int c_dw[4][4] = {{0,0,0,0},{1,0,0,0},{0,0,0,0},{1,0,1,0}};
__constant__ int c_kx[4][4] = {{4,0,0,0},{3,5,0,0},{1,7,0,0},{0,2,6,8}};

// ---------------------------------------------------------------------------
// Helpers
// ---------------------------------------------------------------------------
__device__ __forceinline__ float tf32r(float x) {
    uint32_t u;
    asm("cvt.rna.tf32.f32 %0, %1;" : "=r"(u) : "f"(x));
    return __uint_as_float(u);
}
__device__ __forceinline__ uint32_t smem_u32(const void* p) {
    uint32_t a;
    asm("{ .reg .u64 t; cvta.to.shared.u64 t, %1; cvt.u32.u64 %0, t; }"
        : "=r"(a) : "l"(p));
    return a;
}
__device__ __forceinline__ void ldsm4(uint32_t &r0, uint32_t &r1,
                                      uint32_t &r2, uint32_t &r3, uint32_t a) {
    asm volatile("ldmatrix.sync.aligned.m8n8.x4.shared.b16 {%0,%1,%2,%3}, [%4];"
                 : "=r"(r0), "=r"(r1), "=r"(r2), "=r"(r3) : "r"(a));
}
// m16n8k8 tf32: A 4 regs, B 2 regs, C 4 regs (fp32)
__device__ __forceinline__ void mma_tf32(float* c, const uint32_t* a,
                                         const uint32_t* b) {
    asm volatile(
        "mma.sync.aligned.m16n8k8.row.col.f32.tf32.tf32.f32 "
        "{%0,%1,%2,%3}, {%4,%5,%6,%7}, {%8,%9}, {%0,%1,%2,%3};"
        : "+f"(c[0]), "+f"(c[1]), "+f"(c[2]), "+f"(c[3])
        : "r"(a[0]), "r"(a[1]), "r"(a[2]), "r"(a[3]), "r"(b[0]), "r"(b[1]));
}
__device__ __forceinline__ void cpa16(uint32_t dst, const void* src, int sz) {
    asm volatile("cp.async.cg.shared.global [%0], [%1], 16, %2;"
                 :: "r"(dst), "l"(src), "r"(sz) : "memory");
}
__device__ __forceinline__ void cpa_commit() {
    asm volatile("cp.async.commit_group;" ::: "memory");
}

// rows are 128B (32 tf32); 8 slots of 16B; XOR-swizzle -> conflict-free ldsm
__device__ __forceinline__ uint32_t swz(int row, int j16) {
    return (uint32_t)(row * 128 + ((j16 ^ (row & 7)) * 16));
}

// ---------------------------------------------------------------------------
// K0: zero segment counters
// ---------------------------------------------------------------------------
__global__ void k_zero() {
    if (threadIdx.x < 8) g_cnt[threadIdx.x] = 0;
}

// ---------------------------------------------------------------------------
// K1: input NCHW -> NHWC, tf32-rounded
// ---------------------------------------------------------------------------
__global__ void k_tin(const float* __restrict__ x) {
    __shared__ float t[32][33];
    int b  = blockIdx.z;
    int p0 = blockIdx.x * 32;
    int c0 = blockIdx.y * 32;
    int tx = threadIdx.x, ty = threadIdx.y;
#pragma unroll
    for (int r = 0; r < 4; r++) {
        int c = c0 + ty + r * 8;
        t[ty + r * 8][tx] = x[((b * CINC + c) << 12) + p0 + tx];
    }
    __syncthreads();
#pragma unroll
    for (int r = 0; r < 4; r++) {
        int p = p0 + ty + r * 8;
        g_xT[((b << 12) + p) * CINC + c0 + tx] = tf32r(t[tx][ty + r * 8]);
    }
}

// ---------------------------------------------------------------------------
// K2: weight relayout, tf32-rounded
// ---------------------------------------------------------------------------
__global__ void k_tw(const float* __restrict__ wh,
                     const float* __restrict__ wl2,
                     const float* __restrict__ wl1) {
    int idx = blockIdx.x * blockDim.x + threadIdx.x;
    if (idx < 9 * CINC * COUTC) {
        int ci = idx / (COUTC * 9);
        int r  = idx % (COUTC * 9);
        int co = r / 9, t = r % 9;
        g_wh[(t * COUTC + co) * CINC + ci] = tf32r(wh[idx]);
    }
    if (idx < 9 * CMIDC * COUTC) {
        int cm = idx / (COUTC * 9);
        int r  = idx % (COUTC * 9);
        int co = r / 9, t = r % 9;
        g_wl2[(t * COUTC + co) * CMIDC + cm] = tf32r(wl2[idx]);
    }
    if (idx < CMIDC * CINC) {
        g_w1[idx] = tf32r(wl1[idx]);      // already [cm][ci]
    }
}

// ---------------------------------------------------------------------------
// K3: bottleneck GEMM via tf32 HMMA.  mid = x @ w1^T + b_low1.
//     128px/CTA, N=64, Kc=32 (8 chunks). 8 warps of 32px x 32cm.
//     Small smem (50KB) -> 2 CTAs/SM for cross-CTA latency hiding.
// ---------------------------------------------------------------------------
#define MD_BIAS 0
#define MD_A    1024
#define MD_ASZ  16384
#define MD_B    (MD_A + 2*MD_ASZ)
#define MD_BSZ  8192
#define MD_SMEM (MD_B + 2*MD_BSZ)     // 50176

__global__ __launch_bounds__(256, 2)
void k_mid(const float* __restrict__ b_low1) {
    extern __shared__ char sm[];
    int tid = threadIdx.x;
    int m0  = blockIdx.x * 128;
    uint32_t sb = smem_u32(sm);
    float* sbias = (float*)(sm + MD_BIAS);
    if (tid < 64) sbias[tid] = b_low1[tid];

    int wid = tid >> 5, lane = tid & 31;
    int wm = wid & 3, wn = wid >> 2;    // 4 x 32px, 2 x 32cm
    int lg = lane >> 3, lr = lane & 7;  // ldmatrix group / row-in-group
    float acc[2][4][4];
#pragma unroll
    for (int i = 0; i < 2; i++)
#pragma unroll
        for (int j = 0; j < 4; j++)
#pragma unroll
            for (int k = 0; k < 4; k++) acc[i][j][k] = 0.f;

    int arow = tid >> 1, aj0 = (tid & 1) * 4;   // 128 rows, 4 cpa16/thread
    int brow = tid >> 2, bj0 = (tid & 3) * 2;   // 64 rows, 2 cpa16/thread

    auto stage = [&](int c, int buf) {
        int koff = c * 32;
        const char* as = (const char*)(g_xT + (size_t)(m0 + arow) * CINC + koff);
        const char* bs = (const char*)(g_w1 + (size_t)brow * CINC + koff);
        uint32_t dA = sb + MD_A + buf * MD_ASZ;
        uint32_t dB = sb + MD_B + buf * MD_BSZ;
#pragma unroll
        for (int i = 0; i < 4; i++)
            cpa16(dA + swz(arow, aj0 + i), as + (aj0 + i) * 16, 16);
#pragma unroll
        for (int i = 0; i < 2; i++)
            cpa16(dB + swz(brow, bj0 + i), bs + (bj0 + i) * 16, 16);
        cpa_commit();
    };

    stage(0, 0);
    const int nCh = 8;
    for (int c = 0; c < nCh; c++) {
        int buf = c & 1;
        if (c + 1 < nCh) {
            stage(c + 1, buf ^ 1);
            asm volatile("cp.async.wait_group 1;" ::: "memory");
        } else {
            asm volatile("cp.async.wait_group 0;" ::: "memory");
        }
        __syncthreads();
        uint32_t aB = sb + MD_A + buf * MD_ASZ;
        uint32_t bB = sb + MD_B + buf * MD_BSZ;
#pragma unroll
        for (int ks = 0; ks < 4; ks++) {
            int j16 = ks * 2 + (lg >> 1);
            uint32_t a[2][4], bt[4][2];
#pragma unroll
            for (int mi = 0; mi < 2; mi++) {
                int row = wm * 32 + mi * 16 + (lg & 1) * 8 + lr;
                ldsm4(a[mi][0], a[mi][1], a[mi][2], a[mi][3], aB + swz(row, j16));
            }
#pragma unroll
            for (int gp = 0; gp < 2; gp++) {
                int row = wn * 32 + gp * 16 + (lg & 1) * 8 + lr;
                uint32_t r0, r1, r2, r3;
                ldsm4(r0, r1, r2, r3, bB + swz(row, j16));
                bt[2 * gp][0] = r0;     bt[2 * gp][1] = r2;
                bt[2 * gp + 1][0] = r1; bt[2 * gp + 1][1] = r3;
            }
#pragma unroll
            for (int mi = 0; mi < 2; mi++)
#pragma unroll
                for (int ni = 0; ni < 4; ni++)
                    mma_tf32(acc[mi][ni], a[mi], bt[ni]);
        }
        __syncthreads();
    }

    // epilogue: + bias, tf32-round, store
#pragma unroll
    for (int mi = 0; mi < 2; mi++)
#pragma unroll
        for (int hb = 0; hb < 2; hb++) {
            int rloc = wm * 32 + mi * 16 + hb * 8 + (lane >> 2);
            int pix = m0 + rloc;
#pragma unroll
            for (int ni = 0; ni < 4; ni++)
#pragma unroll
                for (int e = 0; e < 2; e++) {
                    int cm = wn * 32 + ni * 8 + (lane & 3) * 2 + e;
                    g_mid[(size_t)pix * CMIDC + cm] =
                        tf32r(acc[mi][ni][hb * 2 + e] + sbias[cm]);
                }
        }
}

// ---------------------------------------------------------------------------
// K4: per-phase mask compaction
// ---------------------------------------------------------------------------
__global__ void k_compact(const float* __restrict__ mask) {
    int phase = blockIdx.y, py = phase >> 1, px = phase & 1;
    int tid = threadIdx.x;
    int pid = blockIdx.x * 256 + tid;
    int b = pid >> 12, h = (pid >> 6) & 63, w = pid & 63;
    float mv = mask[(b * HOUT + 2 * h + py) * WOUT + 2 * w + px];
    bool hi = mv > 0.5f;

    __shared__ int cHi[8], oHi[8], oLo[8];
    __shared__ int bHi, bLo;
    int lane = tid & 31, wd = tid >> 5;
    unsigned bal = __ballot_sync(0xffffffffu, hi);
    if (lane == 0) cHi[wd] = __popc(bal);
    __syncthreads();
    if (tid == 0) {
        int sh = 0, sl = 0;
        for (int i = 0; i < 8; i++) {
            oHi[i] = sh; sh += cHi[i];
            oLo[i] = sl; sl += 32 - cHi[i];
        }
        bHi = atomicAdd(&g_cnt[phase], sh);
        bLo = atomicAdd(&g_cnt[4 + phase], sl);
    }
    __syncthreads();
    unsigned lt = (1u << lane) - 1u;
    if (hi) g_list[phase][bHi + oHi[wd] + __popc(bal & lt)] = pid;
    else    g_list[4 + phase][bLo + oLo[wd] + __popc((~bal) & lt)] = pid;
}

// ---------------------------------------------------------------------------
// K5: main list-gathered implicit GEMM via tf32 HMMA.
//     CTA = 128 px x 128 co (grid.y co-half), 256 threads,
//     8 warps of 32px x 64co. Kc=32 double-buffered; 66.5KB smem -> 2 CTAs/SM.
// ---------------------------------------------------------------------------
#define KM_SID  0
#define KM_BIAS 512
#define KM_A    1024
#define KM_ASZ  16384
#define KM_B    (KM_A + 2*KM_ASZ)
#define KM_BSZ  16384
#define KM_SMEM (KM_B + 2*KM_BSZ)     // 66560

__global__ __launch_bounds__(256, 2)
void k_main(const float* __restrict__ b_high, const float* __restrict__ b_low2,
            float* __restrict__ out) {
    extern __shared__ char sm[];
    int seg   = blockIdx.z;
    int count = g_cnt[seg];
    int m0    = blockIdx.x * 128;
    if (m0 >= count) return;

    int branch = seg >> 2, phase = seg & 3;
    int py = phase >> 1, px = phase & 1;
    int Kin  = branch ? CMIDC : CINC;
    int cpt  = Kin >> 5;            // Kc=32 chunks per tap: 8 high / 2 low
    int ntap = (py + 1) * (px + 1);
    int nCh  = ntap * cpt;
    const float* Ab = branch ? g_mid : g_xT;
    const float* Wb = branch ? g_wl2 : g_wh;
    const float* bias = branch ? b_low2 : b_high;
    int co0 = blockIdx.y * 128;

    int* sid = (int*)(sm + KM_SID);
    float* sbias = (float*)(sm + KM_BIAS);
    int tid = threadIdx.x;
    if (tid < 128) {
        int m = m0 + tid;
        sid[tid]   = g_list[seg][m < count ? m : count - 1];
        sbias[tid] = bias[co0 + tid];
    }
    __syncthreads();
    uint32_t sb = smem_u32(sm);

    int wid = tid >> 5, lane = tid & 31;
    int wm = wid & 3, wn = wid >> 2;    // 4 x 32px, 2 x 64co
    int lg = lane >> 3, lr = lane & 7;
    float acc[2][8][4];
#pragma unroll
    for (int i = 0; i < 2; i++)
#pragma unroll
        for (int j = 0; j < 8; j++)
#pragma unroll
            for (int k = 0; k < 4; k++) acc[i][j][k] = 0.f;

    int arow = tid >> 1, aj0 = (tid & 1) * 4;   // 128 rows, 4 cpa16/thread
    // B: 128 co rows, same split
    auto stage = [&](int c, int buf) {
        int tap  = c / cpt;
        int koff = (c - tap * cpt) << 5;
        int dh = c_dh[phase][tap], dw = c_dw[phase][tap], kx = c_kx[phase][tap];
        int id = sid[arow];
        int b = id >> 12, h = (id >> 6) & 63, w = id & 63;
        int hh = h + dh, ww = w + dw;
        bool ok = (hh < HH) && (ww < WWD);
        const char* as = (const char*)(Ab +
            (size_t)((((b << 6) + (ok ? hh : h)) << 6) + (ok ? ww : w)) * Kin + koff);
        const char* bs = (const char*)(Wb +
            (size_t)(kx * COUTC + co0 + arow) * Kin + koff);
        uint32_t dA = sb + KM_A + buf * KM_ASZ;
        uint32_t dB = sb + KM_B + buf * KM_BSZ;
        int asz = ok ? 16 : 0;
#pragma unroll
        for (int i = 0; i < 4; i++) {
            uint32_t sw = swz(arow, aj0 + i);
            cpa16(dA + sw, as + (aj0 + i) * 16, asz);
            cpa16(dB + sw, bs + (aj0 + i) * 16, 16);
        }
        cpa_commit();
    };

    stage(0, 0);
    for (int c = 0; c < nCh; c++) {
        int buf = c & 1;
        if (c + 1 < nCh) {
            stage(c + 1, buf ^ 1);
            asm volatile("cp.async.wait_group 1;" ::: "memory");
        } else {
            asm volatile("cp.async.wait_group 0;" ::: "memory");
        }
        __syncthreads();
        uint32_t aB = sb + KM_A + buf * KM_ASZ;
        uint32_t bB = sb + KM_B + buf * KM_BSZ;
#pragma unroll
        for (int ks = 0; ks < 4; ks++) {
            int j16 = ks * 2 + (lg >> 1);
            uint32_t a[2][4], bt[8][2];
#pragma unroll
            for (int mi = 0; mi < 2; mi++) {
                int row = wm * 32 + mi * 16 + (lg & 1) * 8 + lr;
                ldsm4(a[mi][0], a[mi][1], a[mi][2], a[mi][3], aB + swz(row, j16));
            }
#pragma unroll
            for (int gp = 0; gp < 4; gp++) {
                int row = wn * 64 + gp * 16 + (lg & 1) * 8 + lr;
                uint32_t r0, r1, r2, r3;
                ldsm4(r0, r1, r2, r3, bB + swz(row, j16));
                bt[2 * gp][0] = r0;     bt[2 * gp][1] = r2;
                bt[2 * gp + 1][0] = r1; bt[2 * gp + 1][1] = r3;
            }
#pragma unroll
            for (int mi = 0; mi < 2; mi++)
#pragma unroll
                for (int ni = 0; ni < 8; ni++)
                    mma_tf32(acc[mi][ni], a[mi], bt[ni]);
        }
        __syncthreads();
    }

    // epilogue: + bias, scatter to NCHW
#pragma unroll
    for (int mi = 0; mi < 2; mi++)
#pragma unroll
        for (int hb = 0; hb < 2; hb++) {
            int rloc = wm * 32 + mi * 16 + hb * 8 + (lane >> 2);
            if (m0 + rloc >= count) continue;
            int id = sid[rloc];
            int b = id >> 12, h = (id >> 6) & 63, w = id & 63;
            int ho = 2 * h + py, wo = 2 * w + px;
            float* op = out + (((size_t)b * COUTC + co0) * HOUT + ho) * WOUT + wo;
#pragma unroll
            for (int ni = 0; ni < 8; ni++) {
                int n0 = wn * 64 + ni * 8 + (lane & 3) * 2;
                op[(size_t)n0 * (HOUT * WOUT)] =
                    acc[mi][ni][hb * 2 + 0] + sbias[n0];
                op[(size_t)(n0 + 1) * (HOUT * WOUT)] =
                    acc[mi][ni][hb * 2 + 1] + sbias[n0 + 1];
            }
        }
}

// ---------------------------------------------------------------------------
// launch
// Inputs (metadata order): inx, mask, inv_mask, w_high, b_high,
//                          w_low1, b_low1, w_low2, b_low2
// ---------------------------------------------------------------------------
extern "C" void kernel_launch(void* const* d_in, const int* in_sizes, int n_in,
                              void* d_out, int out_size) {
    const float* inx    = (const float*)d_in[0];
    const float* mask   = (const float*)d_in[1];
    const float* w_high = (const float*)d_in[3];
    const float* b_high = (const float*)d_in[4];
    const float* w_low1 = (const float*)d_in[5];
    const float* b_low1 = (const float*)d_in[6];
    const float* w_low2 = (const float*)d_in[7];
    const float* b_low2 = (const float*)d_in[8];
    float* out = (float*)d_out;

    cudaFuncSetAttribute(k_mid,  cudaFuncAttributeMaxDynamicSharedMemorySize,
                         MD_SMEM);
    cudaFuncSetAttribute(k_main, cudaFuncAttributeMaxDynamicSharedMemorySize,
                         KM_SMEM);

    k_zero<<<1, 32>>>();
    k_tin<<<dim3(128, 8, BB), dim3(32, 8)>>>(inx);
    k_tw<<<(9 * CINC * COUTC + 255) / 256, 256>>>(w_high, w_low2, w_low1);
    k_mid<<<NPIX / 128, 256, MD_SMEM>>>(b_low1);
    k_compact<<<dim3(NPIX / 256, 4), 256>>>(mask);
    k_main<<<dim3(NPIX / 128, 2, 8), 256, KM_SMEM>>>(b_high, b_low2, out);
}